// round 9
// baseline (speedup 1.0000x reference)
#include <cuda_runtime.h>
#include <math.h>

#define Bq   4
#define Nn   192
#define Hh   128
#define NBt  3
#define ROWS (Bq*Nn)       // 768
#define EMAX (ROWS*Nn)
#define TE   32            // edges per tile
#define FST  12            // feature stride (floats)
#define SHS  36            // sh row stride (floats)
#define GRID_E 740
#define RN   4             // rows per CTA in node-side kernels

typedef unsigned long long ull;

// ---- scratch (device globals) ----
__device__ __align__(16) float g_F[ROWS*Hh];
__device__ __align__(16) float g_preA[ROWS*Hh];
__device__ __align__(16) float g_preB[ROWS*Hh];
__device__ __align__(16) float g_agg[ROWS*Hh];
__device__ int   g_cnt[ROWS];
__device__ int   g_nE;
__device__ int   g_eI[EMAX];
__device__ int   g_eJ[EMAX];
__device__ __align__(16) float g_feat[(size_t)EMAX*FST];
__device__ __align__(16) float g_Wc[NBt*256*Hh];
__device__ __align__(16) float g_cvec[NBt*Hh];

__device__ __forceinline__ float silu_f(float x) { return x / (1.0f + __expf(-x)); }
__device__ __forceinline__ ull fma2(ull a, ull b, ull c) {
    ull d; asm("fma.rn.f32x2 %0, %1, %2, %3;" : "=l"(d) : "l"(a), "l"(b), "l"(c)); return d;
}
__device__ __forceinline__ ull pack2(float lo, float hi) {
    ull d; asm("mov.b64 %0, {%1, %2};" : "=l"(d) : "f"(lo), "f"(hi)); return d;
}
__device__ __forceinline__ void unpack2(ull v, float& lo, float& hi) {
    asm("mov.b64 {%0, %1}, %2;" : "=f"(lo), "=f"(hi) : "l"(v));
}

// feats = emb[idx]; preA/preB block 0; RN rows per CTA (weight traffic /RN)
__global__ void k_init(const int* __restrict__ idx, const float* __restrict__ emb,
                       const float* __restrict__ ew1, float* __restrict__ out) {
    int h = threadIdx.x;
    int r0 = blockIdx.x * RN;
    __shared__ __align__(16) float xs[RN][Hh];
    #pragma unroll
    for (int r = 0; r < RN; r++) {
        float v = emb[idx[r0+r]*Hh + h];
        g_F[(r0+r)*Hh + h] = v;
        xs[r][h] = v;
        g_agg[(r0+r)*Hh + h] = 0.f;
    }
    if (blockIdx.x == 0) {
        if (h < Bq) out[h] = 0.f;
        if (h == 0) g_nE = 0;
    }
    __syncthreads();
    const float* W1a = ew1;            // block 0
    const float* W1b = ew1 + Hh*Hh;
    float a[RN], bv[RN];
    #pragma unroll
    for (int r = 0; r < RN; r++) { a[r] = 0.f; bv[r] = 0.f; }
    for (int k = 0; k < Hh; k += 4) {
        float wa0 = W1a[(k+0)*Hh+h], wa1 = W1a[(k+1)*Hh+h];
        float wa2 = W1a[(k+2)*Hh+h], wa3 = W1a[(k+3)*Hh+h];
        float wb0 = W1b[(k+0)*Hh+h], wb1 = W1b[(k+1)*Hh+h];
        float wb2 = W1b[(k+2)*Hh+h], wb3 = W1b[(k+3)*Hh+h];
        #pragma unroll
        for (int r = 0; r < RN; r++) {
            float4 x = *(const float4*)&xs[r][k];
            a[r]  += x.x*wa0 + x.y*wa1 + x.z*wa2 + x.w*wa3;
            bv[r] += x.x*wb0 + x.y*wb1 + x.z*wb2 + x.w*wb3;
        }
    }
    #pragma unroll
    for (int r = 0; r < RN; r++) {
        g_preA[(r0+r)*Hh + h] = a[r];
        g_preB[(r0+r)*Hh + h] = bv[r];
    }
}

// flat edge list + block-invariant geometry features
__global__ void k_edges(const float* __restrict__ pos, const int* __restrict__ adj,
                        const float* __restrict__ mask,
                        const float* __restrict__ dpw, const float* __restrict__ dpb) {
    int row = blockIdx.x;
    int b = row / Nn, i = row % Nn;
    int j = threadIdx.x;
    __shared__ int s_cnt, s_base;
    if (j == 0) s_cnt = 0;
    __syncthreads();

    const float* pb = pos + (size_t)b*Nn*3;
    float xi = pb[i*3+0], yi = pb[i*3+1], zi = pb[i*3+2];
    float xj = pb[j*3+0], yj = pb[j*3+1], zj = pb[j*3+2];
    float dx = xi-xj, dy = yi-yj, dz = zi-zj;
    float dist = sqrtf(dx*dx + dy*dy + dz*dz);
    bool valid = (mask[row] > 0.f) && (mask[b*Nn + j] > 0.f) && (dist <= 5.0f)
                 && (adj[(size_t)b*Nn*Nn + (size_t)i*Nn + j] > 0) && (i != j);
    int el = -1;
    float ft[10];
    if (valid) {
        el = atomicAdd(&s_cnt, 1);
        float inv = 1.0f / (dist + 1e-8f);
        float ux = dx*inv, uy = dy*inv, uz = dz*inv;
        const float w = (5.0f/6.0f) + 1e-8f;
        #pragma unroll
        for (int r = 0; r < 6; r++) {
            float t = (dist - (float)r) / w;
            ft[r] = expf(-0.5f * t * t);
        }
        #pragma unroll
        for (int s = 0; s < 4; s++) {
            float vv = ux*dpw[0*4+s] + uy*dpw[1*4+s] + uz*dpw[2*4+s] + dpb[s];
            ft[6+s] = tanhf(vv);
        }
    }
    __syncthreads();
    if (j == 0) {
        g_cnt[row] = s_cnt;
        s_base = atomicAdd(&g_nE, s_cnt);
    }
    __syncthreads();
    if (valid) {
        int e = s_base + el;
        g_eI[e] = row;
        g_eJ[e] = b*Nn + j;
        float4* fo = (float4*)&g_feat[(size_t)e*FST];
        fo[0] = make_float4(ft[0], ft[1], ft[2], ft[3]);
        fo[1] = make_float4(ft[4], ft[5], ft[6], ft[7]);
        fo[2] = make_float4(ft[8], ft[9], 0.f, 0.f);
    }
}

// weight folding, RN fold-rows per CTA. grid = 3*65: per t, 64 row-blocks + 1 cvec block
__global__ void k_fold(const float* __restrict__ rw2, const float* __restrict__ rb2,
                       const float* __restrict__ dw2, const float* __restrict__ db2,
                       const float* __restrict__ ew1, const float* __restrict__ eb1) {
    int h   = threadIdx.x;
    int t   = blockIdx.x / 65;
    int sub = blockIdx.x % 65;
    const float* W1c = ew1 + (size_t)t*4*Hh*Hh + 2*Hh*Hh;
    const float* W1d = W1c + Hh*Hh;
    if (sub < 64) {
        int kk0 = sub * RN;                 // 4-aligned, never straddles 128
        __shared__ __align__(16) float srow[RN][Hh];
        const float* W = (kk0 < 128) ? W1c : W1d;
        #pragma unroll
        for (int r = 0; r < RN; r++) {
            int kk = kk0 + r;
            const float* src = (kk < 128) ? (rw2 + ((size_t)t*128 + kk)*Hh)
                                          : (dw2 + ((size_t)t*128 + kk - 128)*Hh);
            srow[r][h] = src[h];
        }
        __syncthreads();
        float acc[RN];
        #pragma unroll
        for (int r = 0; r < RN; r++) acc[r] = 0.f;
        for (int m = 0; m < Hh; m += 4) {
            float w0 = W[(m+0)*Hh+h], w1 = W[(m+1)*Hh+h];
            float w2 = W[(m+2)*Hh+h], w3 = W[(m+3)*Hh+h];
            #pragma unroll
            for (int r = 0; r < RN; r++) {
                float4 x = *(const float4*)&srow[r][m];
                acc[r] += x.x*w0 + x.y*w1 + x.z*w2 + x.w*w3;
            }
        }
        #pragma unroll
        for (int r = 0; r < RN; r++)
            g_Wc[(size_t)(t*256 + kk0 + r)*Hh + h] = acc[r];
    } else {
        __shared__ float rb[Hh], db[Hh];
        rb[h] = rb2[t*Hh + h];
        db[h] = db2[t*Hh + h];
        __syncthreads();
        float s = eb1[t*Hh + h];
        #pragma unroll 4
        for (int m = 0; m < Hh; m++) s += rb[m]*W1c[m*Hh + h] + db[m]*W1d[m*Hh + h];
        g_cvec[t*Hh + h] = s;
    }
}

// Edge MLP + aggregation: 32-edge tiles, WH=4, 8 edges/warp (unchanged from R8)
__global__ void __launch_bounds__(Hh, 5)
k_edge_mlp(const float* __restrict__ rw1, const float* __restrict__ rb1,
           const float* __restrict__ dw1, const float* __restrict__ db1, int t) {
    __shared__ __align__(16) float sh[256*SHS];
    __shared__ int s_eI[TE], s_eJ[TE];
    int tid  = threadIdx.x;
    int hq   = tid & 31;
    int grp  = tid >> 5;
    int eoff = grp * 8;

    int nE = g_nE;
    int nT = (nE + TE - 1) / TE;
    const float* Wc = g_Wc + (size_t)t*256*Hh;
    float4 cv = *(const float4*)&g_cvec[t*Hh + 4*hq];

    for (int tile = blockIdx.x; tile < nT; tile += gridDim.x) {
        int e0 = tile * TE;
        int ne = min(TE, nE - e0);
        __syncthreads();
        if (tid < TE) {
            int idx = (tid < ne) ? (e0 + tid) : e0;
            s_eI[tid] = g_eI[idx];
            s_eJ[tid] = g_eJ[idx];
        }
        {
            float rb1h = rb1[t*Hh + tid], db1h = db1[t*Hh + tid];
            float rw[6], dwv[4];
            #pragma unroll
            for (int r = 0; r < 6; r++) rw[r] = rw1[(t*6 + r)*Hh + tid];
            #pragma unroll
            for (int r = 0; r < 4; r++) dwv[r] = dw1[(t*4 + r)*Hh + tid];
            #pragma unroll
            for (int q = 0; q < 4; q++) {
                float va[8], vb[8];
                #pragma unroll
                for (int e = 0; e < 8; e++) {
                    int ge = q*8 + e;
                    if (ge < ne) {
                        const float4* fp = (const float4*)&g_feat[(size_t)(e0+ge)*FST];
                        float4 fa = fp[0], fb4 = fp[1], fc = fp[2];
                        float a = rb1h + fa.x*rw[0] + fa.y*rw[1] + fa.z*rw[2]
                                       + fa.w*rw[3] + fb4.x*rw[4] + fb4.y*rw[5];
                        float bb = db1h + fb4.z*dwv[0] + fb4.w*dwv[1]
                                        + fc.x*dwv[2] + fc.y*dwv[3];
                        va[e] = silu_f(a);
                        vb[e] = silu_f(bb);
                    } else { va[e] = 0.f; vb[e] = 0.f; }
                }
                float4* rowA = (float4*)&sh[tid*SHS + q*8];
                float4* rowB = (float4*)&sh[(128+tid)*SHS + q*8];
                rowA[0] = make_float4(va[0], va[1], va[2], va[3]);
                rowA[1] = make_float4(va[4], va[5], va[6], va[7]);
                rowB[0] = make_float4(vb[0], vb[1], vb[2], vb[3]);
                rowB[1] = make_float4(vb[4], vb[5], vb[6], vb[7]);
            }
        }
        __syncthreads();

        ull acc[4][4];
        #pragma unroll
        for (int p = 0; p < 4; p++) {
            int ea = eoff + 2*p, eb = ea + 1;
            float4 a0 = *(const float4*)&g_preA[s_eI[ea]*Hh + 4*hq];
            float4 b0 = *(const float4*)&g_preB[s_eJ[ea]*Hh + 4*hq];
            float4 a1 = *(const float4*)&g_preA[s_eI[eb]*Hh + 4*hq];
            float4 b1 = *(const float4*)&g_preB[s_eJ[eb]*Hh + 4*hq];
            acc[0][p] = pack2(a0.x + b0.x + cv.x, a1.x + b1.x + cv.x);
            acc[1][p] = pack2(a0.y + b0.y + cv.y, a1.y + b1.y + cv.y);
            acc[2][p] = pack2(a0.z + b0.z + cv.z, a1.z + b1.z + cv.z);
            acc[3][p] = pack2(a0.w + b0.w + cv.w, a1.w + b1.w + cv.w);
        }

        #pragma unroll 4
        for (int k = 0; k < 256; k++) {
            float4 w = __ldg((const float4*)&Wc[k*Hh + 4*hq]);
            ull w0 = pack2(w.x, w.x), w1 = pack2(w.y, w.y);
            ull w2 = pack2(w.z, w.z), w3 = pack2(w.w, w.w);
            const float* row = &sh[k*SHS + eoff];
            ulonglong2 sA = *(const ulonglong2*)(row);
            ulonglong2 sB = *(const ulonglong2*)(row + 4);
            acc[0][0]=fma2(sA.x,w0,acc[0][0]); acc[0][1]=fma2(sA.y,w0,acc[0][1]);
            acc[0][2]=fma2(sB.x,w0,acc[0][2]); acc[0][3]=fma2(sB.y,w0,acc[0][3]);
            acc[1][0]=fma2(sA.x,w1,acc[1][0]); acc[1][1]=fma2(sA.y,w1,acc[1][1]);
            acc[1][2]=fma2(sB.x,w1,acc[1][2]); acc[1][3]=fma2(sB.y,w1,acc[1][3]);
            acc[2][0]=fma2(sA.x,w2,acc[2][0]); acc[2][1]=fma2(sA.y,w2,acc[2][1]);
            acc[2][2]=fma2(sB.x,w2,acc[2][2]); acc[2][3]=fma2(sB.y,w2,acc[2][3]);
            acc[3][0]=fma2(sA.x,w3,acc[3][0]); acc[3][1]=fma2(sA.y,w3,acc[3][1]);
            acc[3][2]=fma2(sB.x,w3,acc[3][2]); acc[3][3]=fma2(sB.y,w3,acc[3][3]);
        }

        int neH = ne - eoff; neH = neH < 0 ? 0 : (neH > 8 ? 8 : neH);
        #pragma unroll
        for (int c = 0; c < 4; c++) {
            float mv[8];
            #pragma unroll
            for (int p = 0; p < 4; p++) {
                float lo, hi;
                unpack2(acc[c][p], lo, hi);
                mv[2*p] = silu_f(lo); mv[2*p+1] = silu_f(hi);
            }
            int hh = 4*hq + c;
            int cur = -1; float s = 0.f;
            #pragma unroll
            for (int e = 0; e < 8; e++) {
                if (e < neH) {
                    int i = s_eI[eoff + e];
                    if (i != cur) {
                        if (cur >= 0) atomicAdd(&g_agg[cur*Hh + hh], s);
                        cur = i; s = mv[e];
                    } else s += mv[e];
                }
            }
            if (cur >= 0) atomicAdd(&g_agg[cur*Hh + hh], s);
        }
    }
}

// node update, RN rows per CTA (weight traffic /RN). grid = ROWS/RN
__global__ void k_node(const float* __restrict__ ew2, const float* __restrict__ eb2,
                       const float* __restrict__ nw1, const float* __restrict__ nb1,
                       const float* __restrict__ nw2, const float* __restrict__ nb2,
                       const float* __restrict__ ew1,
                       const float* __restrict__ ow1, const float* __restrict__ ob1,
                       const float* __restrict__ ow2, const float* __restrict__ ob2,
                       const float* __restrict__ mask, float* __restrict__ out, int t) {
    int h = threadIdx.x;
    int r0 = blockIdx.x * RN;
    __shared__ __align__(16) float xs[RN][256];
    __shared__ __align__(16) float aggs[RN][Hh];
    __shared__ __align__(16) float us[RN][Hh];
    __shared__ float red[RN][4];

    float fh[RN];
    #pragma unroll
    for (int r = 0; r < RN; r++) {
        fh[r] = g_F[(r0+r)*Hh + h];
        xs[r][h] = fh[r];
        aggs[r][h] = g_agg[(r0+r)*Hh + h];
    }
    __syncthreads();

    // stage 1: aggOut = agg@ew2 + deg*eb2
    const float* EW2 = ew2 + (size_t)t*Hh*Hh;
    float e2 = eb2[t*Hh + h];
    float s[RN];
    #pragma unroll
    for (int r = 0; r < RN; r++) s[r] = (float)g_cnt[r0+r] * e2;
    for (int k = 0; k < Hh; k += 4) {
        float w0 = EW2[(k+0)*Hh+h], w1 = EW2[(k+1)*Hh+h];
        float w2 = EW2[(k+2)*Hh+h], w3 = EW2[(k+3)*Hh+h];
        #pragma unroll
        for (int r = 0; r < RN; r++) {
            float4 a = *(const float4*)&aggs[r][k];
            s[r] += a.x*w0 + a.y*w1 + a.z*w2 + a.w*w3;
        }
    }
    #pragma unroll
    for (int r = 0; r < RN; r++) xs[r][Hh + h] = s[r];
    __syncthreads();

    // stage 2: u = silu([f, aggOut] @ nw1 + nb1)
    const float* NW1 = nw1 + (size_t)t*256*Hh;
    float b1 = nb1[t*Hh + h];
    float u[RN];
    #pragma unroll
    for (int r = 0; r < RN; r++) u[r] = b1;
    for (int k = 0; k < 256; k += 4) {
        float w0 = NW1[(k+0)*Hh+h], w1 = NW1[(k+1)*Hh+h];
        float w2 = NW1[(k+2)*Hh+h], w3 = NW1[(k+3)*Hh+h];
        #pragma unroll
        for (int r = 0; r < RN; r++) {
            float4 x = *(const float4*)&xs[r][k];
            u[r] += x.x*w0 + x.y*w1 + x.z*w2 + x.w*w3;
        }
    }
    #pragma unroll
    for (int r = 0; r < RN; r++) us[r][h] = silu_f(u[r]);
    __syncthreads();

    // stage 3: upd = u @ nw2 + nb2; f += upd
    const float* NW2 = nw2 + (size_t)t*Hh*Hh;
    float b2v = nb2[t*Hh + h];
    float upd[RN];
    #pragma unroll
    for (int r = 0; r < RN; r++) upd[r] = b2v;
    for (int k = 0; k < Hh; k += 4) {
        float w0 = NW2[(k+0)*Hh+h], w1 = NW2[(k+1)*Hh+h];
        float w2 = NW2[(k+2)*Hh+h], w3 = NW2[(k+3)*Hh+h];
        #pragma unroll
        for (int r = 0; r < RN; r++) {
            float4 x = *(const float4*)&us[r][k];
            upd[r] += x.x*w0 + x.y*w1 + x.z*w2 + x.w*w3;
        }
    }
    float newf[RN];
    #pragma unroll
    for (int r = 0; r < RN; r++) {
        newf[r] = fh[r] + upd[r];
        g_F[(r0+r)*Hh + h] = newf[r];
    }
    __syncthreads();
    #pragma unroll
    for (int r = 0; r < RN; r++) xs[r][h] = newf[r];
    __syncthreads();

    if (t + 1 < NBt) {
        const float* W1a = ew1 + (size_t)(t+1)*4*Hh*Hh;
        const float* W1b = W1a + Hh*Hh;
        float a[RN], bv[RN];
        #pragma unroll
        for (int r = 0; r < RN; r++) { a[r] = 0.f; bv[r] = 0.f; }
        for (int k = 0; k < Hh; k += 4) {
            float wa0 = W1a[(k+0)*Hh+h], wa1 = W1a[(k+1)*Hh+h];
            float wa2 = W1a[(k+2)*Hh+h], wa3 = W1a[(k+3)*Hh+h];
            float wb0 = W1b[(k+0)*Hh+h], wb1 = W1b[(k+1)*Hh+h];
            float wb2 = W1b[(k+2)*Hh+h], wb3 = W1b[(k+3)*Hh+h];
            #pragma unroll
            for (int r = 0; r < RN; r++) {
                float4 x = *(const float4*)&xs[r][k];
                a[r]  += x.x*wa0 + x.y*wa1 + x.z*wa2 + x.w*wa3;
                bv[r] += x.x*wb0 + x.y*wb1 + x.z*wb2 + x.w*wb3;
            }
        }
        #pragma unroll
        for (int r = 0; r < RN; r++) {
            g_preA[(r0+r)*Hh + h] = a[r];
            g_preB[(r0+r)*Hh + h] = bv[r];
            g_agg[(r0+r)*Hh + h] = 0.f;
        }
    } else {
        // output head
        float ob1h = ob1[h], ow2h = ow2[h];
        float o[RN];
        #pragma unroll
        for (int r = 0; r < RN; r++) o[r] = ob1h;
        for (int k = 0; k < Hh; k += 4) {
            float w0 = ow1[(k+0)*Hh+h], w1 = ow1[(k+1)*Hh+h];
            float w2 = ow1[(k+2)*Hh+h], w3 = ow1[(k+3)*Hh+h];
            #pragma unroll
            for (int r = 0; r < RN; r++) {
                float4 x = *(const float4*)&xs[r][k];
                o[r] += x.x*w0 + x.y*w1 + x.z*w2 + x.w*w3;
            }
        }
        #pragma unroll
        for (int r = 0; r < RN; r++) {
            float val = silu_f(o[r]) * ow2h;
            #pragma unroll
            for (int off = 16; off > 0; off >>= 1)
                val += __shfl_down_sync(0xffffffffu, val, off);
            if ((h & 31) == 0) red[r][h >> 5] = val;
        }
        __syncthreads();
        if (h == 0) {
            #pragma unroll
            for (int r = 0; r < RN; r++) {
                float v = red[r][0] + red[r][1] + red[r][2] + red[r][3] + ob2[0];
                v *= mask[r0 + r];
                atomicAdd(&out[(r0 + r) / Nn], v);
            }
        }
    }
}

extern "C" void kernel_launch(void* const* d_in, const int* in_sizes, int n_in,
                              void* d_out, int out_size) {
    const int*   node_indices = (const int*)  d_in[0];
    const float* positions    = (const float*)d_in[1];
    const int*   adjacency    = (const int*)  d_in[2];
    const float* mask         = (const float*)d_in[3];
    const float* emb          = (const float*)d_in[4];
    const float* dpw          = (const float*)d_in[5];
    const float* dpb          = (const float*)d_in[6];
    const float* rbf_w1 = (const float*)d_in[7];
    const float* rbf_b1 = (const float*)d_in[8];
    const float* rbf_w2 = (const float*)d_in[9];
    const float* rbf_b2 = (const float*)d_in[10];
    const float* dir_w1 = (const float*)d_in[11];
    const float* dir_b1 = (const float*)d_in[12];
    const float* dir_w2 = (const float*)d_in[13];
    const float* dir_b2 = (const float*)d_in[14];
    const float* edge_w1 = (const float*)d_in[15];
    const float* edge_b1 = (const float*)d_in[16];
    const float* edge_w2 = (const float*)d_in[17];
    const float* edge_b2 = (const float*)d_in[18];
    const float* node_w1 = (const float*)d_in[19];
    const float* node_b1 = (const float*)d_in[20];
    const float* node_w2 = (const float*)d_in[21];
    const float* node_b2 = (const float*)d_in[22];
    const float* ow1 = (const float*)d_in[23];
    const float* ob1 = (const float*)d_in[24];
    const float* ow2 = (const float*)d_in[25];
    const float* ob2 = (const float*)d_in[26];
    float* out = (float*)d_out;

    k_init<<<ROWS/RN, Hh>>>(node_indices, emb, edge_w1, out);   // resets g_nE
    k_edges<<<ROWS, Nn>>>(positions, adjacency, mask, dpw, dpb);
    k_fold<<<3*65, Hh>>>(rbf_w2, rbf_b2, dir_w2, dir_b2, edge_w1, edge_b1);
    for (int t = 0; t < NBt; t++) {
        k_edge_mlp<<<GRID_E, Hh>>>(rbf_w1, rbf_b1, dir_w1, dir_b1, t);
        k_node<<<ROWS/RN, Hh>>>(edge_w2, edge_b2, node_w1, node_b1, node_w2, node_b2,
                                edge_w1, ow1, ob1, ow2, ob2, mask, out, t);
    }
}